// round 4
// baseline (speedup 1.0000x reference)
#include <cuda_runtime.h>

#define NB    16384
#define SN    81
#define HID   32
#define OBSW  162
#define BPB   8
#define NTHREADS (BPB * 32)
#define SPAN  19
#define TOTQ  (SN * SPAN)   // 1539
#define NIT   49            // ceil(1539/32)
#define UNR   7

// out layout: [0,NB) symbolic | [NB,2NB) imm | [2NB,3NB) next | [3NB,..) nsc BxSN

__global__ __launch_bounds__(NTHREADS) void gdvpn_kernel(
    const float* __restrict__ obs,
    const float* __restrict__ ac,
    const float* __restrict__ W1,
    const float* __restrict__ W2,
    const float* __restrict__ W3,
    const float* __restrict__ b3,
    float* __restrict__ out)
{
    // sh[w][5*j+off] = ac[b, j, j+D[off]] or 0; D = {-9,-1,0,+1,+9}
    __shared__ float sh[BPB][SN * 5];
    __shared__ float sh_nsc[BPB][SN];

    const int w    = threadIdx.x >> 5;
    const int lane = threadIdx.x & 31;
    const int b    = blockIdx.x * BPB + w;
    const float* acb = ac + (size_t)b * (SN * SN);

    // ---- Phase 1: contiguous-span gather (dense DRAM bursts) ----
    // q enumerates the 19-float span around each row's diagonal:
    //   j = q/19, d = q%19 - 9, addr = 82*j + d.
    #pragma unroll
    for (int base = 0; base < NIT; base += UNR) {
        float v[UNR];
        int   qq[UNR];
        #pragma unroll
        for (int u = 0; u < UNR; ++u) {
            const int q = lane + (base + u) * 32;
            qq[u] = q;
            const int j = q / SPAN;
            const int a = 82 * j + (q - j * SPAN - 9);
            v[u] = (q < TOTQ && a >= 0 && a < SN * SN) ? __ldcs(acb + a) : 0.0f;
        }
        #pragma unroll
        for (int u = 0; u < UNR; ++u) {
            const int q = qq[u];
            if (q < TOTQ) {
                const int j = q / SPAN;
                const int d = q - j * SPAN - 9;
                const int c = j % 9;
                // keep only the 5 needed offsets; zero-fill invalid neighbors
                if (d == 0)       sh[w][5 * j + 2] = v[u];
                else if (d == -9) sh[w][5 * j + 0] = (j >= 9)     ? v[u] : 0.0f;
                else if (d == -1) sh[w][5 * j + 1] = (c > 0)      ? v[u] : 0.0f;
                else if (d == 1)  sh[w][5 * j + 3] = (c < 8)      ? v[u] : 0.0f;
                else if (d == 9)  sh[w][5 * j + 4] = (j < SN - 9) ? v[u] : 0.0f;
            }
        }
    }
    __syncwarp();

    // ---- Phase 2: nsc + served ----
    float served = 0.0f;
    #pragma unroll
    for (int k = 0; k < 3; ++k) {
        const int t = lane + k * 32;
        if (t < SN) {
            const int c = t % 9;
            float vv = sh[w][5 * t + 2];
            if (t >= 9)      vv += sh[w][5 * (t - 9) + 4];
            if (t < SN - 9)  vv += sh[w][5 * (t + 9) + 0];
            if (c > 0)       vv += sh[w][5 * (t - 1) + 3];
            if (c < 8)       vv += sh[w][5 * (t + 1) + 1];

            sh_nsc[w][t] = vv;
            out[(size_t)3 * NB + (size_t)b * SN + t] = vv;

            const float demand = __ldg(obs + (size_t)b * OBSW + SN + t);
            served += fminf(vv, demand);
        }
    }

    #pragma unroll
    for (int o = 16; o > 0; o >>= 1)
        served += __shfl_down_sync(0xFFFFFFFFu, served, o);
    const float imm = __shfl_sync(0xFFFFFFFFu, served, 0);
    __syncwarp();

    // ---- Phase 3: MLP (W1/W2 L1-resident) ----
    float h1 = 0.0f;
    #pragma unroll
    for (int i = 0; i < SN; ++i)
        h1 = fmaf(sh_nsc[w][i], __ldg(W1 + i * HID + lane), h1);
    h1 = fmaxf(h1, 0.0f);

    float h2 = 0.0f;
    #pragma unroll
    for (int m = 0; m < HID; ++m)
        h2 = fmaf(__shfl_sync(0xFFFFFFFFu, h1, m), __ldg(W2 + m * HID + lane), h2);
    h2 = fmaxf(h2, 0.0f);

    float contrib = h2 * __ldg(W3 + lane);
    #pragma unroll
    for (int o = 16; o > 0; o >>= 1)
        contrib += __shfl_down_sync(0xFFFFFFFFu, contrib, o);

    if (lane == 0) {
        const float nr = contrib + __ldg(b3);
        out[b]          = imm + nr;
        out[NB + b]     = imm;
        out[2 * NB + b] = nr;
    }
}

extern "C" void kernel_launch(void* const* d_in, const int* in_sizes, int n_in,
                              void* d_out, int out_size)
{
    const float* obs = (const float*)d_in[0];
    const float* ac  = (const float*)d_in[1];
    const float* W1  = (const float*)d_in[2];
    const float* W2  = (const float*)d_in[3];
    const float* W3  = (const float*)d_in[4];
    const float* b3  = (const float*)d_in[5];
    float* out = (float*)d_out;

    gdvpn_kernel<<<NB / BPB, NTHREADS>>>(obs, ac, W1, W2, W3, b3, out);
}

// round 5
// speedup vs baseline: 2.2178x; 2.2178x over previous
#include <cuda_runtime.h>

#define NB    16384
#define SN    81
#define SS    (SN * SN)       // 6561
#define TOT   (NB * SS)       // 107,495,424 (fits int)
#define HID   32
#define OBSW  162
#define BPB   8
#define NTHREADS (BPB * 32)

// out layout: [0,NB) symbolic | [NB,2NB) imm | [2NB,3NB) next | [3NB,..) nsc BxSN

__global__ __launch_bounds__(NTHREADS) void gdvpn_kernel(
    const float* __restrict__ obs,
    const float* __restrict__ ac,
    const float* __restrict__ W1,
    const float* __restrict__ W2,
    const float* __restrict__ W3,
    const float* __restrict__ b3,
    float* __restrict__ out)
{
    // sh[w][5*j+s] = ac[b, j, j+D[s]] or 0; D = {-9,-1,0,+1,+9}
    __shared__ float sh[BPB][SN * 5];
    __shared__ float sh_nsc[BPB][SN];

    const int w    = threadIdx.x >> 5;
    const int lane = threadIdx.x & 31;
    const int b    = blockIdx.x * BPB + w;
    const int sbase = b * SS;

    // pre-zero staging (covers grid-invalid neighbor slots)
    #pragma unroll
    for (int q = lane; q < SN * 5; q += 32) sh[w][q] = 0.0f;
    __syncwarp();

    // ---- Phase 1: per row j, load the float4-aligned 32-float window that
    // contains [82j-9, 82j+9]. 8 lanes x float4 = one contiguous 128B request
    // per row; 4 rows per warp instruction. Global flat addressing keeps
    // 16B alignment (slice stride 6561 is not float4-aligned).
    const int u    = lane & 7;    // float4 index within window
    const int jrow = lane >> 3;   // row within group of 4

    #pragma unroll
    for (int batch = 0; batch < 3; ++batch) {
        float4 v[7];
        int    Av[7];
        #pragma unroll
        for (int k = 0; k < 7; ++k) {
            const int j = 4 * (batch * 7 + k) + jrow;
            if (j < SN) {
                const int G = sbase + 82 * j - 9;     // global addr of window anchor
                int A = G & ~3;
                if (A < 0) A = 0;
                if (A > TOT - 32) A = TOT - 32;
                Av[k] = A;
                v[k] = __ldg(reinterpret_cast<const float4*>(ac + A) + u);
            }
        }
        #pragma unroll
        for (int k = 0; k < 7; ++k) {
            const int j = 4 * (batch * 7 + k) + jrow;
            if (j < SN) {
                const int G = sbase + 82 * j - 9;
                const int base_p = G - Av[k];          // anchor offset in window
                const int c = j % 9;
                const bool val0 = (j >= 9);      // d = -9
                const bool val1 = (c > 0);       // d = -1
                const bool val3 = (c < 8);       // d = +1
                const bool val4 = (j < SN - 9);  // d = +9
                // slot positions within window: base_p + {0, 8, 9, 10, 18}
                #pragma unroll
                for (int s = 0; s < 5; ++s) {
                    const int P = (s == 0) ? 0 : (s == 1) ? 8 : (s == 2) ? 9 : (s == 3) ? 10 : 18;
                    const bool ok = (s == 0) ? val0 : (s == 1) ? val1 : (s == 2) ? true
                                  : (s == 3) ? val3 : val4;
                    const int p = base_p + P;
                    if (ok && (p >> 2) == u) {
                        const int m = p & 3;
                        const float x = (m == 0) ? v[k].x : (m == 1) ? v[k].y
                                      : (m == 2) ? v[k].z : v[k].w;
                        sh[w][5 * j + s] = x;
                    }
                }
            }
        }
    }
    __syncwarp();

    // ---- Phase 2: nsc + served ----
    float served = 0.0f;
    #pragma unroll
    for (int k = 0; k < 3; ++k) {
        const int t = lane + k * 32;
        if (t < SN) {
            const int c = t % 9;
            float vv = sh[w][5 * t + 2];
            if (t >= 9)      vv += sh[w][5 * (t - 9) + 4];
            if (t < SN - 9)  vv += sh[w][5 * (t + 9) + 0];
            if (c > 0)       vv += sh[w][5 * (t - 1) + 3];
            if (c < 8)       vv += sh[w][5 * (t + 1) + 1];

            sh_nsc[w][t] = vv;
            out[(size_t)3 * NB + (size_t)b * SN + t] = vv;

            const float demand = __ldg(obs + (size_t)b * OBSW + SN + t);
            served += fminf(vv, demand);
        }
    }

    #pragma unroll
    for (int o = 16; o > 0; o >>= 1)
        served += __shfl_down_sync(0xFFFFFFFFu, served, o);
    const float imm = __shfl_sync(0xFFFFFFFFu, served, 0);
    __syncwarp();

    // ---- Phase 3: MLP (W1/W2 L1-resident) ----
    float h1 = 0.0f;
    #pragma unroll
    for (int i = 0; i < SN; ++i)
        h1 = fmaf(sh_nsc[w][i], __ldg(W1 + i * HID + lane), h1);
    h1 = fmaxf(h1, 0.0f);

    float h2 = 0.0f;
    #pragma unroll
    for (int m = 0; m < HID; ++m)
        h2 = fmaf(__shfl_sync(0xFFFFFFFFu, h1, m), __ldg(W2 + m * HID + lane), h2);
    h2 = fmaxf(h2, 0.0f);

    float contrib = h2 * __ldg(W3 + lane);
    #pragma unroll
    for (int o = 16; o > 0; o >>= 1)
        contrib += __shfl_down_sync(0xFFFFFFFFu, contrib, o);

    if (lane == 0) {
        const float nr = contrib + __ldg(b3);
        out[b]          = imm + nr;
        out[NB + b]     = imm;
        out[2 * NB + b] = nr;
    }
}

extern "C" void kernel_launch(void* const* d_in, const int* in_sizes, int n_in,
                              void* d_out, int out_size)
{
    const float* obs = (const float*)d_in[0];
    const float* ac  = (const float*)d_in[1];
    const float* W1  = (const float*)d_in[2];
    const float* W2  = (const float*)d_in[3];
    const float* W3  = (const float*)d_in[4];
    const float* b3  = (const float*)d_in[5];
    float* out = (float*)d_out;

    gdvpn_kernel<<<NB / BPB, NTHREADS>>>(obs, ac, W1, W2, W3, b3, out);
}

// round 6
// speedup vs baseline: 2.2797x; 1.0279x over previous
#include <cuda_runtime.h>

#define NB    16384
#define SN    81
#define HID   32
#define OBSW  162
#define BPB   8
#define NTHREADS (BPB * 32)

// out layout: [0,NB) symbolic | [NB,2NB) imm | [2NB,3NB) next | [3NB,..) nsc BxSN

// Gather load with minimal L2 fill-size hint (probe: does this shrink the
// 128B-per-miss DRAM fill granularity observed in R1-R5?)
__device__ __forceinline__ float ld_small(const float* p) {
    float v;
    asm("ld.global.L2::64B.f32 %0, [%1];" : "=f"(v) : "l"(p));
    return v;
}

__global__ __launch_bounds__(NTHREADS) void gdvpn_kernel(
    const float* __restrict__ obs,   // B x 162
    const float* __restrict__ ac,    // B x 81 x 81
    const float* __restrict__ W1,    // 81 x 32
    const float* __restrict__ W2,    // 32 x 32
    const float* __restrict__ W3,    // 32
    const float* __restrict__ b3,    // 1
    float* __restrict__ out)
{
    // sh[w][5*j+off] = ac[b, j, j+D[off]] (0 if invalid), D = {-9,-1,0,+1,+9}.
    // Stride 5 coprime with 32 -> conflict-free LDS.
    __shared__ float sh[BPB][SN * 5];
    __shared__ float sh_nsc[BPB][SN];

    const int w    = threadIdx.x >> 5;   // warp id = slice within block
    const int lane = threadIdx.x & 31;
    const int b    = blockIdx.x * BPB + w;
    const float* acb = ac + (size_t)b * (SN * SN);

    // ---- Phase 1: gather (13 independent predicated loads per lane) ----
    #pragma unroll
    for (int it = 0; it < 13; ++it) {
        const int q = lane + it * 32;
        if (q < SN * 5) {
            const int j   = q / 5;
            const int off = q - 5 * j;
            const int c   = j % 9;
            int d; bool valid;
            switch (off) {
                case 0: d = -9; valid = (j >= 9);     break;
                case 1: d = -1; valid = (c > 0);      break;
                case 2: d =  0; valid = true;         break;
                case 3: d =  1; valid = (c < 8);      break;
                default:d =  9; valid = (j < SN - 9); break;
            }
            sh[w][q] = valid ? ld_small(acb + 82 * j + d) : 0.0f;
        }
    }
    __syncwarp();

    // ---- Phase 2: nsc + served (lane owns t = lane, lane+32, lane+64) ----
    float served = 0.0f;
    #pragma unroll
    for (int k = 0; k < 3; ++k) {
        const int t = lane + k * 32;
        if (t < SN) {
            const int c = t % 9;
            float v = sh[w][5 * t + 2];                       // j = t
            if (t >= 9)      v += sh[w][5 * (t - 9) + 4];     // j = t-9
            if (t < SN - 9)  v += sh[w][5 * (t + 9) + 0];     // j = t+9
            if (c > 0)       v += sh[w][5 * (t - 1) + 3];     // j = t-1
            if (c < 8)       v += sh[w][5 * (t + 1) + 1];     // j = t+1

            sh_nsc[w][t] = v;
            out[(size_t)3 * NB + (size_t)b * SN + t] = v;

            const float demand = __ldg(obs + (size_t)b * OBSW + SN + t);
            served += fminf(v, demand);
        }
    }

    // warp-reduce served -> immediate reward
    #pragma unroll
    for (int o = 16; o > 0; o >>= 1)
        served += __shfl_down_sync(0xFFFFFFFFu, served, o);
    const float imm = __shfl_sync(0xFFFFFFFFu, served, 0);
    __syncwarp();

    // ---- Phase 3: MLP (W1/W2 L1-resident) ----
    float h1 = 0.0f;
    #pragma unroll
    for (int i = 0; i < SN; ++i)
        h1 = fmaf(sh_nsc[w][i], __ldg(W1 + i * HID + lane), h1);
    h1 = fmaxf(h1, 0.0f);

    float h2 = 0.0f;
    #pragma unroll
    for (int m = 0; m < HID; ++m)
        h2 = fmaf(__shfl_sync(0xFFFFFFFFu, h1, m), __ldg(W2 + m * HID + lane), h2);
    h2 = fmaxf(h2, 0.0f);

    float contrib = h2 * __ldg(W3 + lane);
    #pragma unroll
    for (int o = 16; o > 0; o >>= 1)
        contrib += __shfl_down_sync(0xFFFFFFFFu, contrib, o);

    if (lane == 0) {
        const float nr = contrib + __ldg(b3);
        out[b]          = imm + nr;
        out[NB + b]     = imm;
        out[2 * NB + b] = nr;
    }
}

extern "C" void kernel_launch(void* const* d_in, const int* in_sizes, int n_in,
                              void* d_out, int out_size)
{
    const float* obs = (const float*)d_in[0];
    const float* ac  = (const float*)d_in[1];
    const float* W1  = (const float*)d_in[2];
    const float* W2  = (const float*)d_in[3];
    const float* W3  = (const float*)d_in[4];
    const float* b3  = (const float*)d_in[5];
    float* out = (float*)d_out;

    gdvpn_kernel<<<NB / BPB, NTHREADS>>>(obs, ac, W1, W2, W3, b3, out);
}